// round 8
// baseline (speedup 1.0000x reference)
#include <cuda_runtime.h>
#include <math.h>

// ---------------- problem constants ----------------
#define Dm   1024
#define Hh   16
#define DH   64
#define DFF  4096
#define DC   768
#define Tt   2048
#define Bb   2
#define Cc   77
#define MX   4096          // Bb*Tt rows of x

// ---------------- scratch (static device arrays; no allocs) ----------------
__device__ float g_ln   [(size_t)MX * Dm];
__device__ float g_qkv  [(size_t)MX * 3 * Dm];
__device__ float g_attn [(size_t)MX * Dm];
__device__ float g_x1   [(size_t)MX * Dm];
__device__ float g_x2   [(size_t)MX * Dm];
__device__ float g_qca  [(size_t)MX * Dm];
__device__ float g_kvca [(size_t)Bb * Cc * 2 * Dm];
__device__ float g_ff   [(size_t)MX * DFF];
__device__ float g_w    [(size_t)16400000];          // tf32-rounded weights + cond

// weight-scratch offsets (floats) - contiguous, in rounding order
#define SZ_QKV  (Dm*3*Dm)
#define SZ_PSA  (Dm*Dm)
#define SZ_QCA  (Dm*Dm)
#define SZ_KVCA (DC*2*Dm)
#define SZ_PCA  (Dm*Dm)
#define SZ_FF1  (Dm*DFF)
#define SZ_FF2  (DFF*Dm)
#define SZ_COND (Bb*Cc*DC)
#define OW_QKV   0
#define OW_PSA   (OW_QKV + SZ_QKV)
#define OW_QCA   (OW_PSA + SZ_PSA)
#define OW_KVCA  (OW_QCA + SZ_QCA)
#define OW_PCA   (OW_KVCA + SZ_KVCA)
#define OW_FF1   (OW_PCA + SZ_PCA)
#define OW_FF2   (OW_FF1 + SZ_FF1)
#define OW_COND  (OW_FF2 + SZ_FF2)
#define OW_TOT   (OW_COND + SZ_COND)

// ---------------- tf32 helpers ----------------
__device__ __forceinline__ unsigned totf(float f) {
    unsigned u;
    asm("cvt.rna.tf32.f32 %0, %1;" : "=r"(u) : "f"(f));
    return u;
}
__device__ __forceinline__ float totf_f(float f) { return __uint_as_float(totf(f)); }

__device__ __forceinline__ void mma_tf32(float c[4],
    unsigned a0, unsigned a1, unsigned a2, unsigned a3,
    unsigned b0, unsigned b1)
{
    asm volatile(
        "mma.sync.aligned.m16n8k8.row.col.f32.tf32.tf32.f32 "
        "{%0,%1,%2,%3}, {%4,%5,%6,%7}, {%8,%9}, {%0,%1,%2,%3};\n"
        : "+f"(c[0]), "+f"(c[1]), "+f"(c[2]), "+f"(c[3])
        : "r"(a0), "r"(a1), "r"(a2), "r"(a3), "r"(b0), "r"(b1));
}

__device__ __forceinline__ void cpa16(unsigned dst, const float* src, bool pred) {
    int sz = pred ? 16 : 0;
    asm volatile("cp.async.cg.shared.global [%0], [%1], 16, %2;\n"
                 :: "r"(dst), "l"(src), "r"(sz));
}
__device__ __forceinline__ void cpa16u(unsigned dst, const float* src) {
    asm volatile("cp.async.cg.shared.global [%0], [%1], 16;\n"
                 :: "r"(dst), "l"(src));
}
__device__ __forceinline__ void cpa_commit() {
    asm volatile("cp.async.commit_group;\n");
}
template<int N>
__device__ __forceinline__ void cpa_wait() {
    asm volatile("cp.async.wait_group %0;\n" :: "n"(N));
}

// ---------------- merged weight rounding prep (one launch) ----------------
__global__ __launch_bounds__(256) void round_all_kernel(
    const float* __restrict__ s0, const float* __restrict__ s1,
    const float* __restrict__ s2, const float* __restrict__ s3,
    const float* __restrict__ s4, const float* __restrict__ s5,
    const float* __restrict__ s6, const float* __restrict__ s7,
    float* __restrict__ dst)
{
    int n4 = OW_TOT / 4;
    for (int i = blockIdx.x * 256 + threadIdx.x; i < n4; i += gridDim.x * 256) {
        int idx = i * 4;
        const float* src;
        if      (idx < OW_PSA)  src = s0 + (idx - OW_QKV);
        else if (idx < OW_QCA)  src = s1 + (idx - OW_PSA);
        else if (idx < OW_KVCA) src = s2 + (idx - OW_QCA);
        else if (idx < OW_PCA)  src = s3 + (idx - OW_KVCA);
        else if (idx < OW_FF1)  src = s4 + (idx - OW_PCA);
        else if (idx < OW_FF2)  src = s5 + (idx - OW_FF1);
        else if (idx < OW_COND) src = s6 + (idx - OW_FF2);
        else                    src = s7 + (idx - OW_COND);
        float4 v = *(const float4*)src;
        v.x = totf_f(v.x); v.y = totf_f(v.y);
        v.z = totf_f(v.z); v.w = totf_f(v.w);
        *(float4*)(dst + idx) = v;
    }
}

// ---------------- reductions ----------------
__device__ __forceinline__ float block_sum(float v, float* sh) {
    #pragma unroll
    for (int o = 16; o > 0; o >>= 1) v += __shfl_xor_sync(0xffffffffu, v, o);
    int w = threadIdx.x >> 5;
    if ((threadIdx.x & 31) == 0) sh[w] = v;
    __syncthreads();
    if (threadIdx.x < 32) {
        float t = (threadIdx.x < 8) ? sh[threadIdx.x] : 0.f;
        #pragma unroll
        for (int o = 4; o > 0; o >>= 1) t += __shfl_xor_sync(0xffffffffu, t, o);
        if (threadIdx.x == 0) sh[0] = t;
    }
    __syncthreads();
    float r = sh[0];
    __syncthreads();
    return r;
}

// ---------------- LayerNorm (tf32-rounded output) ----------------
__global__ __launch_bounds__(256) void ln_kernel(
    const float* __restrict__ x, const float* __restrict__ g,
    const float* __restrict__ b, float* __restrict__ out)
{
    __shared__ float sh[8];
    long row = blockIdx.x;
    const float4* xr = (const float4*)(x + row * Dm);
    int tid = threadIdx.x;
    float4 v = xr[tid];
    float s = v.x + v.y + v.z + v.w;
    s = block_sum(s, sh);
    float mean = s * (1.0f / Dm);
    float dx = v.x - mean, dy = v.y - mean, dz = v.z - mean, dw = v.w - mean;
    float s2 = dx*dx + dy*dy + dz*dz + dw*dw;
    s2 = block_sum(s2, sh);
    float rstd = rsqrtf(s2 * (1.0f / Dm) + 1e-5f);
    float4 gg = ((const float4*)g)[tid];
    float4 bbv = ((const float4*)b)[tid];
    float4 o;
    o.x = totf_f(dx * rstd * gg.x + bbv.x);
    o.y = totf_f(dy * rstd * gg.y + bbv.y);
    o.z = totf_f(dz * rstd * gg.z + bbv.z);
    o.w = totf_f(dw * rstd * gg.w + bbv.w);
    ((float4*)(out + row * Dm))[tid] = o;
}

// ================= fused flash attention (tf32, cp.async K/V double-buffer) =========
#define FBQ 128
#define FBK 64
#define FSQ 68
#define FSV 72
#define KVW (FBK*FSQ + FBK*FSV)                 // 8960 words per KV stage
#define FSMEM ((FBQ*FSQ + 2*KVW) * 4)           // 106496 bytes

__global__ __launch_bounds__(256, 2) void flash_kernel(
    const float* __restrict__ Qp, const float* __restrict__ Kp,
    const float* __restrict__ Vp, float* __restrict__ Op,
    int Tq, int Tk, int ldq, int ldk, int ldo,
    long sQb, long sQh, long sKb, long sKh, long sOb, long sOh,
    int Hn, float scale, int causal)
{
    extern __shared__ unsigned fsm[];
    unsigned* Qs = fsm;
    unsigned sbase = (unsigned)__cvta_generic_to_shared(fsm);

    int z = blockIdx.z, zb = z / Hn, zh = z - zb * Hn;
    Qp += zb * sQb + zh * sQh;
    Kp += zb * sKb + zh * sKh;
    Vp += zb * sKb + zh * sKh;
    Op += zb * sOb + zh * sOh;

    int tid = threadIdx.x, lane = tid & 31, warp = tid >> 5;
    int gid = lane >> 2, tg = lane & 3;
    int row0 = blockIdx.y * FBQ;

    // ---- Q tile (sync load, exact pow2 scale folded) ----
    #pragma unroll
    for (int it = 0; it < 8; it++) {
        int idx = it * 256 + tid;
        int r = idx >> 4, c4 = (idx & 15) * 4;
        int gr = row0 + r;
        float4 v = make_float4(0.f, 0.f, 0.f, 0.f);
        if (gr < Tq) v = *(const float4*)(Qp + (long)gr * ldq + c4);
        unsigned* q = &Qs[r * FSQ + c4];
        q[0] = __float_as_uint(v.x * scale); q[1] = __float_as_uint(v.y * scale);
        q[2] = __float_as_uint(v.z * scale); q[3] = __float_as_uint(v.w * scale);
    }

    // ---- K/V async loader: 64 rows x 64 floats each; 8 cp.async per thread ----
    int lr  = tid >> 2;                  // row 0..63
    int lc0 = (tid & 3) * 16;            // col base {0,16,32,48}
    auto load_kv = [&](int t, int buf) {
        int kvb = t * FBK;
        unsigned kb = sbase + (FBQ * FSQ + buf * KVW) * 4;
        unsigned vb = kb + FBK * FSQ * 4;
        const float* ksrc = Kp + (long)(kvb + lr) * ldk + lc0;
        const float* vsrc = Vp + (long)(kvb + lr) * ldk + lc0;
        bool ok = (kvb + lr) < Tk;
        unsigned kdst = kb + (lr * FSQ + lc0) * 4;
        unsigned vdst = vb + (lr * FSV + lc0) * 4;
        #pragma unroll
        for (int i = 0; i < 4; i++) {
            cpa16(kdst + i * 16, ksrc + i * 4, ok);
            cpa16(vdst + i * 16, vsrc + i * 4, ok);
        }
    };

    int r_0 = row0 + warp * 16 + gid;
    int r_1 = r_0 + 8;

    float m0 = -1e30f, m1 = -1e30f, l0 = 0.f, l1 = 0.f;
    float o[8][4];
    #pragma unroll
    for (int i = 0; i < 8; i++)
        #pragma unroll
        for (int j = 0; j < 4; j++) o[i][j] = 0.f;

    int ntile = causal ? (row0 + FBQ) / FBK : (Tk + FBK - 1) / FBK;

    load_kv(0, 0);
    cpa_commit();

    for (int t = 0; t < ntile; t++) {
        cpa_wait<0>();
        __syncthreads();          // tile t ready; all warps done with buf t^1
        if (t + 1 < ntile) { load_kv(t + 1, (t + 1) & 1); cpa_commit(); }

        int buf = t & 1;
        const unsigned* Ks = fsm + FBQ * FSQ + buf * KVW;
        const unsigned* Vs = Ks + FBK * FSQ;
        int kvb = t * FBK;

        // ---- S = Q @ K^T ----
        float sacc[8][4];
        #pragma unroll
        for (int i = 0; i < 8; i++)
            #pragma unroll
            for (int j = 0; j < 4; j++) sacc[i][j] = 0.f;

        #pragma unroll
        for (int ks = 0; ks < 8; ks++) {
            int qb = (warp * 16 + gid) * FSQ + ks * 8 + tg;
            unsigned qa0 = Qs[qb];
            unsigned qa1 = Qs[qb + 8 * FSQ];
            unsigned qa2 = Qs[qb + 4];
            unsigned qa3 = Qs[qb + 8 * FSQ + 4];
            #pragma unroll
            for (int ni = 0; ni < 8; ni++) {
                int kb = (ni * 8 + gid) * FSQ + ks * 8 + tg;
                mma_tf32(sacc[ni], qa0, qa1, qa2, qa3, Ks[kb], Ks[kb + 4]);
            }
        }

        bool domask = (causal && (kvb + FBK - 1 > row0)) || (kvb + FBK > Tk);
        if (domask) {
            #pragma unroll
            for (int ni = 0; ni < 8; ni++) {
                #pragma unroll
                for (int s = 0; s < 4; s++) {
                    int col = kvb + ni * 8 + tg * 2 + (s & 1);
                    int r = (s < 2) ? r_0 : r_1;
                    bool ok = (col < Tk) && (!causal || col <= r);
                    if (!ok) sacc[ni][s] = -1e30f;
                }
            }
        }

        // ---- online softmax ----
        float tm0 = -1e30f, tm1 = -1e30f;
        #pragma unroll
        for (int ni = 0; ni < 8; ni++) {
            tm0 = fmaxf(tm0, fmaxf(sacc[ni][0], sacc[ni][1]));
            tm1 = fmaxf(tm1, fmaxf(sacc[ni][2], sacc[ni][3]));
        }
        tm0 = fmaxf(tm0, __shfl_xor_sync(0xffffffffu, tm0, 1));
        tm0 = fmaxf(tm0, __shfl_xor_sync(0xffffffffu, tm0, 2));
        tm1 = fmaxf(tm1, __shfl_xor_sync(0xffffffffu, tm1, 1));
        tm1 = fmaxf(tm1, __shfl_xor_sync(0xffffffffu, tm1, 2));

        float nm0 = fmaxf(m0, tm0), nm1 = fmaxf(m1, tm1);
        float sc0 = __expf(m0 - nm0), sc1 = __expf(m1 - nm1);
        m0 = nm0; m1 = nm1;

        float rs0 = 0.f, rs1 = 0.f;
        #pragma unroll
        for (int ni = 0; ni < 8; ni++) {
            sacc[ni][0] = __expf(sacc[ni][0] - nm0); rs0 += sacc[ni][0];
            sacc[ni][1] = __expf(sacc[ni][1] - nm0); rs0 += sacc[ni][1];
            sacc[ni][2] = __expf(sacc[ni][2] - nm1); rs1 += sacc[ni][2];
            sacc[ni][3] = __expf(sacc[ni][3] - nm1); rs1 += sacc[ni][3];
        }
        rs0 += __shfl_xor_sync(0xffffffffu, rs0, 1);
        rs0 += __shfl_xor_sync(0xffffffffu, rs0, 2);
        rs1 += __shfl_xor_sync(0xffffffffu, rs1, 1);
        rs1 += __shfl_xor_sync(0xffffffffu, rs1, 2);
        l0 = l0 * sc0 + rs0;
        l1 = l1 * sc1 + rs1;

        #pragma unroll
        for (int ni = 0; ni < 8; ni++) {
            o[ni][0] *= sc0; o[ni][1] *= sc0;
            o[ni][2] *= sc1; o[ni][3] *= sc1;
        }

        // ---- O += P @ V ----
        int bl = lane & ~3;
        int s0 = bl + (tg >> 1);
        int s1 = bl + 2 + (tg >> 1);
        bool hi = (tg & 1);
        #pragma unroll
        for (int ks = 0; ks < 8; ks++) {
            float p0 = sacc[ks][0], p1 = sacc[ks][1];
            float p2 = sacc[ks][2], p3 = sacc[ks][3];
            float v00 = __shfl_sync(0xffffffffu, p0, s0);
            float v01 = __shfl_sync(0xffffffffu, p1, s0);
            float v10 = __shfl_sync(0xffffffffu, p2, s0);
            float v11 = __shfl_sync(0xffffffffu, p3, s0);
            float w00 = __shfl_sync(0xffffffffu, p0, s1);
            float w01 = __shfl_sync(0xffffffffu, p1, s1);
            float w10 = __shfl_sync(0xffffffffu, p2, s1);
            float w11 = __shfl_sync(0xffffffffu, p3, s1);
            unsigned a0 = totf(hi ? v01 : v00);
            unsigned a1 = totf(hi ? v11 : v10);
            unsigned a2 = totf(hi ? w01 : w00);
            unsigned a3 = totf(hi ? w11 : w10);
            #pragma unroll
            for (int nj = 0; nj < 8; nj++) {
                int vb = (ks * 8 + tg) * FSV + nj * 8 + gid;
                mma_tf32(o[nj], a0, a1, a2, a3, Vs[vb], Vs[vb + 4 * FSV]);
            }
        }
    }

    float inv0 = 1.0f / l0, inv1 = 1.0f / l1;
    #pragma unroll
    for (int nj = 0; nj < 8; nj++) {
        int c = nj * 8 + tg * 2;
        if (r_0 < Tq) {
            float2 w = make_float2(totf_f(o[nj][0] * inv0), totf_f(o[nj][1] * inv0));
            *(float2*)(Op + (long)r_0 * ldo + c) = w;
        }
        if (r_1 < Tq) {
            float2 w = make_float2(totf_f(o[nj][2] * inv1), totf_f(o[nj][3] * inv1));
            *(float2*)(Op + (long)r_1 * ldo + c) = w;
        }
    }
}

// ================= cp.async 4-stage tf32 GEMM, 128x256 block, 64x64 warp tile ========
#define BM 128
#define BN 256
#define BK 16
#define NSTG 4
#define SAS 20
#define SBS 264
#define AW (BM * SAS)
#define BW (BK * SBS)
#define STG (AW + BW)
#define GSMEM (STG * NSTG * 4)

template<int EPI>
__global__ __launch_bounds__(256, 1) void tgemm(
    const float* __restrict__ A, const float* __restrict__ Bm,
    const float* __restrict__ bias, const float* __restrict__ Res,
    float* __restrict__ C,
    int M, int N, int K, int lda, int ldb)
{
    extern __shared__ unsigned dsm[];
    unsigned sbase = (unsigned)__cvta_generic_to_shared(dsm);

    int row0 = blockIdx.y * BM, col0 = blockIdx.x * BN;
    int tid  = threadIdx.x;
    int lane = tid & 31, warp = tid >> 5;
    int wm = (warp & 1) * 64;
    int wn = (warp >> 1) * 64;
    int gid = lane >> 2, tg = lane & 3;

    int ar = tid >> 1;
    int ak = (tid & 1) * 8;
    int bk = tid >> 6;
    int bn = (tid & 63) * 4;

    auto load_stage = [&](int s, int k0) {
        unsigned abase = sbase + (s * STG) * 4;
        unsigned bbase = sbase + (s * STG + AW) * 4;
        const float* asrc = A + (long)(row0 + ar) * lda + k0 + ak;
        bool av = (row0 + ar) < M;
        unsigned adst = abase + (ar * SAS + ak) * 4;
        cpa16(adst, asrc, av);
        cpa16(adst + 16, asrc + 4, av);
        const float* bsrc = Bm + (long)(k0 + bk) * ldb + col0 + bn;
        unsigned bdst = bbase + (bk * SBS + bn) * 4;
        #pragma unroll
        for (int i = 0; i < 4; i++)
            cpa16u(bdst + i * (SBS * 4 * 4), bsrc + (long)(4 * i) * ldb);
    };

    float acc[4][8][4];
    #pragma unroll
    for (int i = 0; i < 4; i++)
        #pragma unroll
        for (int j = 0; j < 8; j++)
            #pragma unroll
            for (int r = 0; r < 4; r++) acc[i][j][r] = 0.f;

    int ntiles = K / BK;

    #pragma unroll
    for (int s = 0; s < NSTG - 1; s++) {
        if (s < ntiles) load_stage(s, s * BK);
        cpa_commit();
    }

    for (int t = 0; t < ntiles; t++) {
        cpa_wait<NSTG - 2>();
        __syncthreads();

        int tn = t + NSTG - 1;
        if (tn < ntiles) load_stage(tn % NSTG, tn * BK);
        cpa_commit();

        int buf = t % NSTG;
        const unsigned* As = dsm + buf * STG;
        const unsigned* Bs = dsm + buf * STG + AW;

        #pragma unroll
        for (int ks = 0; ks < 2; ks++) {
            int k0s = ks * 8;
            unsigned a[4][4], b[8][2];
            #pragma unroll
            for (int mi = 0; mi < 4; mi++) {
                int r = wm + mi * 16 + gid;
                a[mi][0] = As[r * SAS + k0s + tg];
                a[mi][1] = As[(r + 8) * SAS + k0s + tg];
                a[mi][2] = As[r * SAS + k0s + tg + 4];
                a[mi][3] = As[(r + 8) * SAS + k0s + tg + 4];
            }
            #pragma unroll
            for (int ni = 0; ni < 8; ni++) {
                int n = wn + ni * 8 + gid;
                b[ni][0] = Bs[(k0s + tg) * SBS + n];
                b[ni][1] = Bs[(k0s + tg + 4) * SBS + n];
            }
            #pragma unroll
            for (int mi = 0; mi < 4; mi++)
                #pragma unroll
                for (int ni = 0; ni < 8; ni++)
                    mma_tf32(acc[mi][ni], a[mi][0], a[mi][1], a[mi][2], a[mi][3],
                             b[ni][0], b[ni][1]);
        }
    }

    #pragma unroll
    for (int mi = 0; mi < 4; mi++) {
        #pragma unroll
        for (int rr = 0; rr < 2; rr++) {
            int r = row0 + wm + mi * 16 + gid + rr * 8;
            if (r >= M) continue;
            #pragma unroll
            for (int ni = 0; ni < 8; ni++) {
                int c = col0 + wn + ni * 8 + tg * 2;
                float v0 = acc[mi][ni][rr * 2 + 0];
                float v1 = acc[mi][ni][rr * 2 + 1];
                if (EPI & 1) { v0 += bias[c]; v1 += bias[c + 1]; }
                if (EPI & 4) {
                    v0 = 0.5f * v0 * (1.0f + erff(v0 * 0.70710678118654752f));
                    v1 = 0.5f * v1 * (1.0f + erff(v1 * 0.70710678118654752f));
                }
                if (EPI & 2) {
                    float2 rv = *(const float2*)(Res + (long)r * N + c);
                    v0 += rv.x; v1 += rv.y;
                }
                if (EPI & 8) { v0 = totf_f(v0); v1 = totf_f(v1); }
                *(float2*)(C + (long)r * N + c) = make_float2(v0, v1);
            }
        }
    }
}

// ---------------- host side ----------------
static inline dim3 ggrid(int M, int N) {
    return dim3((unsigned)((N + BN - 1) / BN), (unsigned)((M + BM - 1) / BM), 1);
}

extern "C" void kernel_launch(void* const* d_in, const int* in_sizes, int n_in,
                              void* d_out, int out_size)
{
    const float* x        = (const float*)d_in[0];
    const float* cond     = (const float*)d_in[1];
    const float* Wqkv     = (const float*)d_in[2];
    const float* Wproj_sa = (const float*)d_in[3];
    const float* bproj_sa = (const float*)d_in[4];
    const float* g1       = (const float*)d_in[5];
    const float* b1       = (const float*)d_in[6];
    const float* Wq_ca    = (const float*)d_in[7];
    const float* Wkv_ca   = (const float*)d_in[8];
    const float* Wproj_ca = (const float*)d_in[9];
    const float* bproj_ca = (const float*)d_in[10];
    const float* g2       = (const float*)d_in[11];
    const float* b2       = (const float*)d_in[12];
    const float* Wff1     = (const float*)d_in[13];
    const float* bff1     = (const float*)d_in[14];
    const float* Wff2     = (const float*)d_in[15];
    const float* bff2     = (const float*)d_in[16];
    const float* g3       = (const float*)d_in[17];
    const float* b3       = (const float*)d_in[18];
    float* out            = (float*)d_out;

    float *p_ln, *p_qkv, *p_attn, *p_x1, *p_x2, *p_qca, *p_kvca, *p_ff, *p_w;
    cudaGetSymbolAddress((void**)&p_ln,   g_ln);
    cudaGetSymbolAddress((void**)&p_qkv,  g_qkv);
    cudaGetSymbolAddress((void**)&p_attn, g_attn);
    cudaGetSymbolAddress((void**)&p_x1,   g_x1);
    cudaGetSymbolAddress((void**)&p_x2,   g_x2);
    cudaGetSymbolAddress((void**)&p_qca,  g_qca);
    cudaGetSymbolAddress((void**)&p_kvca, g_kvca);
    cudaGetSymbolAddress((void**)&p_ff,   g_ff);
    cudaGetSymbolAddress((void**)&p_w,    g_w);

    static int smem_set = 0;
    if (!smem_set) {
        cudaFuncSetAttribute(flash_kernel, cudaFuncAttributeMaxDynamicSharedMemorySize, FSMEM);
        cudaFuncSetAttribute(tgemm<8>,  cudaFuncAttributeMaxDynamicSharedMemorySize, GSMEM);
        cudaFuncSetAttribute(tgemm<3>,  cudaFuncAttributeMaxDynamicSharedMemorySize, GSMEM);
        cudaFuncSetAttribute(tgemm<13>, cudaFuncAttributeMaxDynamicSharedMemorySize, GSMEM);
        smem_set = 1;
    }

    const long T3D = (long)Tt * 3 * Dm;
    const long TD  = (long)Tt * Dm;
    const long KVb = (long)Cc * 2 * Dm;
    const float iscale = 0.125f;

    // 0) tf32-round all weights + cond into scratch (single launch)
    round_all_kernel<<<2048, 256>>>(Wqkv, Wproj_sa, Wq_ca, Wkv_ca,
                                    Wproj_ca, Wff1, Wff2, cond, p_w);

    // 1) ln1 = LN(x)
    ln_kernel<<<MX, 256>>>(x, g1, b1, p_ln);

    // 2) qkv = ln1 @ Wqkv   (rounded output -> flash inputs)
    tgemm<8><<<ggrid(MX, 3*Dm), 256, GSMEM>>>(
        p_ln, p_w + OW_QKV, nullptr, nullptr, p_qkv, MX, 3*Dm, Dm, Dm, 3*Dm);

    // 3) fused causal self-attention -> g_attn
    flash_kernel<<<dim3(1, Tt/FBQ, Bb*Hh), 256, FSMEM>>>(
        p_qkv, p_qkv + Dm, p_qkv + 2*Dm, p_attn,
        Tt, Tt, 3*Dm, 3*Dm, Dm,
        T3D, DH, T3D, DH, TD, DH, Hh, iscale, 1);

    // 4) x1 = x + attn @ Wproj_sa + b
    tgemm<3><<<ggrid(MX, Dm), 256, GSMEM>>>(
        p_attn, p_w + OW_PSA, bproj_sa, x, p_x1, MX, Dm, Dm, Dm, Dm);

    // 5) ln2 = LN(x1)
    ln_kernel<<<MX, 256>>>(p_x1, g2, b2, p_ln);

    // 6) q_ca = ln2 @ Wq_ca  (rounded -> flash)
    tgemm<8><<<ggrid(MX, Dm), 256, GSMEM>>>(
        p_ln, p_w + OW_QCA, nullptr, nullptr, p_qca, MX, Dm, Dm, Dm, Dm);

    // 7) kv_ca = cond_r @ Wkv_ca (rounded -> flash)
    tgemm<8><<<ggrid(Bb*Cc, 2*Dm), 256, GSMEM>>>(
        p_w + OW_COND, p_w + OW_KVCA, nullptr, nullptr, p_kvca,
        Bb*Cc, 2*Dm, DC, DC, 2*Dm);

    // 8) fused cross-attention -> g_attn
    flash_kernel<<<dim3(1, Tt/FBQ, Bb*Hh), 256, FSMEM>>>(
        p_qca, p_kvca, p_kvca + Dm, p_attn,
        Tt, Cc, Dm, 2*Dm, Dm,
        TD, DH, KVb, DH, TD, DH, Hh, iscale, 0);

    // 9) x2 = x1 + ca_out @ Wproj_ca + b
    tgemm<3><<<ggrid(MX, Dm), 256, GSMEM>>>(
        p_attn, p_w + OW_PCA, bproj_ca, p_x1, p_x2, MX, Dm, Dm, Dm, Dm);

    // 10) ln3 = LN(x2)
    ln_kernel<<<MX, 256>>>(p_x2, g3, b3, p_ln);

    // 11) ffh = gelu(ln3 @ Wff1 + bff1), rounded
    tgemm<13><<<ggrid(MX, DFF), 256, GSMEM>>>(
        p_ln, p_w + OW_FF1, bff1, nullptr, p_ff, MX, DFF, Dm, Dm, DFF);

    // 12) out = x2 + ffh @ Wff2 + bff2
    tgemm<3><<<ggrid(MX, Dm), 256, GSMEM>>>(
        p_ff, p_w + OW_FF2, bff2, p_x2, out, MX, Dm, DFF, DFF, Dm);
}